// round 16
// baseline (speedup 1.0000x reference)
#include <cuda_runtime.h>
#include <cuda_fp16.h>
#include <cstdint>
#include <math.h>

#define DEVI __device__ __forceinline__

// ---------------- problem constants ----------------
constexpr int CB = 32, CS = 577, CD = 768, CH = 12, CDH = 64, CFF = 3072;
constexpr int MALL = CB * CS;            // 18464 rows
constexpr float LNEPS = 1e-5f;
constexpr int MT = (MALL + 127) / 128;   // 145 m-tiles

// ---------------- device scratch (allocation-free) ----------------
__device__ __half g_h   [MALL * CD];              // LN out (GEMM A)
__device__ __half g_qkv [MALL * 3 * CD];          // q|k|v fp16, row ld = 2304
__device__ __half g_ctx [MALL * CD];              // attention ctx fp16
__device__ float  g_x2  [MALL * CD];              // x + attn_out (fp32 residual)
__device__ __half g_ffn [MALL * CFF];             // GELU out fp16
__device__ __half g_Wqkvt[3 * CD * CD];           // [2304][768] k-major
__device__ float  g_bqkv [3 * CD];
__device__ __half g_Wot  [CD * CD];               // [768][768] k-major
__device__ __half g_W1t  [CFF * CD];              // [3072][768]
__device__ __half g_W2t  [CD * CFF];              // [768][3072]
__device__ int    g_cnt  [MT];                    // Wo tile-completion counters

// ---------------- helpers ----------------
DEVI uint32_t smem_u32(const void* p) {
    uint32_t a;
    asm("{ .reg .u64 t; cvta.to.shared.u64 t, %1; cvt.u32.u64 %0, t; }" : "=r"(a) : "l"(p));
    return a;
}
DEVI void cpa16s(uint32_t dst, const void* g) {
    asm volatile("cp.async.cg.shared.global [%0], [%1], 16;" :: "r"(dst), "l"(g));
}
DEVI void cpa_commit() { asm volatile("cp.async.commit_group;"); }
DEVI void sts_zero16(uint32_t dst) {
    asm volatile("st.shared.v4.b32 [%0], {%1,%1,%1,%1};" :: "r"(dst), "r"(0));
}
DEVI void ldm_x4(uint32_t* r, uint32_t addr) {
    asm volatile("ldmatrix.sync.aligned.m8n8.x4.shared.b16 {%0,%1,%2,%3}, [%4];"
        : "=r"(r[0]), "=r"(r[1]), "=r"(r[2]), "=r"(r[3]) : "r"(addr));
}
DEVI void ldm_x4_t(uint32_t* r, uint32_t addr) {
    asm volatile("ldmatrix.sync.aligned.m8n8.x4.trans.shared.b16 {%0,%1,%2,%3}, [%4];"
        : "=r"(r[0]), "=r"(r[1]), "=r"(r[2]), "=r"(r[3]) : "r"(addr));
}
DEVI void mma16816(float* c, const uint32_t* a, const uint32_t* b) {
    asm volatile(
        "mma.sync.aligned.m16n8k16.row.col.f32.f16.f16.f32 "
        "{%0,%1,%2,%3},{%4,%5,%6,%7},{%8,%9},{%0,%1,%2,%3};"
        : "+f"(c[0]), "+f"(c[1]), "+f"(c[2]), "+f"(c[3])
        : "r"(a[0]), "r"(a[1]), "r"(a[2]), "r"(a[3]), "r"(b[0]), "r"(b[1]));
}

// warp-per-row LN body (row pointer fp32 in, fp16 out)
DEVI void ln_row(const float* __restrict__ xr, const float* __restrict__ w,
                 const float* __restrict__ b, __half* __restrict__ orow, int lane) {
    const float4* x4 = (const float4*)xr;
    float4 v[6];
    float s = 0.f;
    #pragma unroll
    for (int i = 0; i < 6; i++) {
        v[i] = x4[lane + 32 * i];
        s += (v[i].x + v[i].y) + (v[i].z + v[i].w);
    }
    #pragma unroll
    for (int o = 16; o > 0; o >>= 1) s += __shfl_xor_sync(0xffffffffu, s, o);
    float mu = s * (1.f / (float)CD);
    float q = 0.f;
    #pragma unroll
    for (int i = 0; i < 6; i++) {
        float dx = v[i].x - mu, dy = v[i].y - mu, dz = v[i].z - mu, dw = v[i].w - mu;
        q += dx * dx + dy * dy + dz * dz + dw * dw;
    }
    #pragma unroll
    for (int o = 16; o > 0; o >>= 1) q += __shfl_xor_sync(0xffffffffu, q, o);
    float rs = rsqrtf(q * (1.f / (float)CD) + LNEPS);
    #pragma unroll
    for (int i = 0; i < 6; i++) {
        int c = (lane + 32 * i) * 4;
        float4 wv = *(const float4*)(w + c);
        float4 bv = *(const float4*)(b + c);
        *(__half2*)(orow + c) = __floats2half2_rn((v[i].x - mu) * rs * wv.x + bv.x,
                                                  (v[i].y - mu) * rs * wv.y + bv.y);
        *(__half2*)(orow + c + 2) = __floats2half2_rn((v[i].z - mu) * rs * wv.z + bv.z,
                                                      (v[i].w - mu) * rs * wv.w + bv.w);
    }
}

// ---------------- fused prep kernel: weight transposes + bias + LN1 + cnt reset ----------------
constexpr int PREP_BLOCKS = 9223;

DEVI void tr32(const float* __restrict__ src, __half* __restrict__ dst,
               int R, int C, int xb, int yb, int tx, int ty, float* t) {
    int c0 = xb * 32, r0 = yb * 32;
    #pragma unroll
    for (int i = 0; i < 32; i += 8)
        t[(ty + i) * 33 + tx] = src[(long long)(r0 + ty + i) * C + c0 + tx];
    __syncthreads();
    #pragma unroll
    for (int i = 0; i < 32; i += 8)
        dst[(long long)(c0 + ty + i) * R + r0 + tx] = __float2half_rn(t[tx * 33 + ty + i]);
}

__global__ void __launch_bounds__(256) prep_k(
    const float* __restrict__ Wq, const float* __restrict__ Wk, const float* __restrict__ Wv,
    const float* __restrict__ bq, const float* __restrict__ bk, const float* __restrict__ bv,
    const float* __restrict__ Wo, const float* __restrict__ W1, const float* __restrict__ W2,
    const float* __restrict__ x, const float* __restrict__ ln1w, const float* __restrict__ ln1b)
{
    __shared__ float t[32 * 33];
    int bx = blockIdx.x;
    int tid = threadIdx.x, tx = tid & 31, ty = tid >> 5;

    if (bx < 1728) {
        int k0 = (bx % 24) * 32, n0 = (bx / 24) * 32;
        int which = n0 / CD;
        int c0 = n0 % CD, h = c0 >> 6, e0 = c0 & 63;
        const float* W = (which == 0) ? Wq : (which == 1) ? Wk : Wv;
        const float* base = W + (long long)h * CD * CDH;
        #pragma unroll
        for (int i = 0; i < 32; i += 8)
            t[(ty + i) * 33 + tx] = base[(long long)(k0 + ty + i) * CDH + e0 + tx];
        __syncthreads();
        #pragma unroll
        for (int i = 0; i < 32; i += 8)
            g_Wqkvt[(long long)(n0 + ty + i) * CD + k0 + tx] = __float2half_rn(t[tx * 33 + ty + i]);
    } else if (bx < 2304) {
        int idx = bx - 1728;
        tr32(Wo, g_Wot, CD, CD, idx % 24, idx / 24, tx, ty, t);
    } else if (bx < 4608) {
        int idx = bx - 2304;
        tr32(W1, g_W1t, CD, CFF, idx % 96, idx / 96, tx, ty, t);
    } else if (bx < 6912) {
        int idx = bx - 4608;
        tr32(W2, g_W2t, CFF, CD, idx % 24, idx / 24, tx, ty, t);
    } else if (bx < 6915) {
        int i = (bx - 6912) * 256 + tid;
        if (i < 3 * CD) {
            int w = i / CD, c = i % CD;
            g_bqkv[i] = ((w == 0) ? bq : (w == 1) ? bk : bv)[c];
        }
        if (bx == 6912 && tid < MT) g_cnt[tid] = 0;   // reset Wo tile counters
    } else {
        int row = (bx - 6915) * 8 + ty;
        if (row < MALL)
            ln_row(x + (long long)row * CD, ln1w, ln1b, g_h + (long long)row * CD, tx);
    }
}

// =====================================================================
// big-tile fp16 GEMM: C[M,N] = A[M,K] * B[N,K]^T (+epilogue)
// 128x256x64, 16 warps x (32x64), rolling depth-2 B prefetch, 3-stage
// cp.async (166 KB smem; NST=4/221 KB kills the container — 3-for-3).
// Next-stage loads issued in one burst after kc=0 (round-14 best).
// EPI: 1 = +bias, half out; 2 = +bias GELU, half out; 3 = +bias+res, float out
//      4 = +bias+res, float out, then FUSED LN2 (last CTA per m-tile)
// =====================================================================
constexpr int BM = 128, BN = 256, BK = 64, NST = 3;
constexpr int NTHR = 512;
constexpr int LDS_H = BK + 8;              // 72 halves per row (144 B)
constexpr int ATILE = BM * LDS_H;
constexpr int BTILE = BN * LDS_H;
constexpr int STG_H = ATILE + BTILE;       // 27648 halves = 55296 B
constexpr int DSMEM = NST * STG_H * 2;     // 165888 B

template <int EPI>
__global__ void __launch_bounds__(NTHR, 1) hgemm2(
    const __half* __restrict__ A, const __half* __restrict__ B, void* __restrict__ Cv,
    const float* __restrict__ bias, const float* __restrict__ res,
    int M, int N, int K,
    const float* __restrict__ lnw, const float* __restrict__ lnb,
    __half* __restrict__ hout)
{
    extern __shared__ __align__(16) __half sh[];
    uint32_t sbase = smem_u32(sh);

    int m0 = blockIdx.y * BM;
    long long n0 = (long long)blockIdx.x * BN;
    int tid = threadIdx.x, lane = tid & 31, wid = tid >> 5;

    auto loadA = [&](int s, int k0) {
        uint32_t ab = sbase + (uint32_t)(s * STG_H) * 2;
        #pragma unroll
        for (int i = 0; i < 2; i++) {
            int v = tid + i * NTHR;
            int r = v >> 3, cq = (v & 7) << 3;
            uint32_t dst = ab + (uint32_t)(r * LDS_H + cq) * 2;
            int gm = m0 + r;
            if (gm < M) cpa16s(dst, A + (long long)gm * K + k0 + cq);
            else        sts_zero16(dst);
        }
    };
    auto loadB = [&](int s, int k0) {
        uint32_t bb = sbase + (uint32_t)(s * STG_H + ATILE) * 2;
        #pragma unroll
        for (int i = 0; i < 4; i++) {
            int v = tid + i * NTHR;
            int r = v >> 3, cq = (v & 7) << 3;
            uint32_t dst = bb + (uint32_t)(r * LDS_H + cq) * 2;
            cpa16s(dst, B + (n0 + r) * K + k0 + cq);
        }
    };

    int wm = (wid & 3) * 32;          // 0,32,64,96
    int wn = (wid >> 2) * 64;         // 0,64,128,192
    int g = lane >> 2, tg = lane & 3;

    int arow = ((lane >> 3) & 1) * 8 + (lane & 7);
    int acol = (lane >> 4) * 8;
    int brow = ((lane >> 4) & 1) * 8 + (lane & 7);
    int bcol = ((lane >> 3) & 1) * 8;

    float acc[2][8][4];
    #pragma unroll
    for (int i = 0; i < 2; i++)
        #pragma unroll
        for (int j = 0; j < 8; j++)
            #pragma unroll
            for (int q = 0; q < 4; q++) acc[i][j][q] = 0.f;

    int nk = K / BK;
    #pragma unroll
    for (int s = 0; s < NST - 1; s++) { loadA(s, s * BK); loadB(s, s * BK); cpa_commit(); }

    for (int kt = 0; kt < nk; kt++) {
        asm volatile("cp.async.wait_group %0;" :: "n"(NST - 2));
        __syncthreads();

        int st = kt % NST;
        uint32_t abase = sbase + (uint32_t)(st * STG_H) * 2;
        uint32_t bbase = sbase + (uint32_t)(st * STG_H + ATILE) * 2;

        #pragma unroll
        for (int kc = 0; kc < 4; kc++) {
            uint32_t af[2][4];
            #pragma unroll
            for (int i = 0; i < 2; i++)
                ldm_x4(af[i], abase + (uint32_t)((wm + i * 16 + arow) * LDS_H + kc * 16 + acol) * 2);
            uint32_t bf[2][4];
            ldm_x4(bf[0], bbase + (uint32_t)((wn + 0 * 16 + brow) * LDS_H + kc * 16 + bcol) * 2);
            ldm_x4(bf[1], bbase + (uint32_t)((wn + 1 * 16 + brow) * LDS_H + kc * 16 + bcol) * 2);
            #pragma unroll
            for (int p = 0; p < 4; p++) {
                #pragma unroll
                for (int i = 0; i < 2; i++) {
                    mma16816(acc[i][2 * p],     af[i], bf[p & 1]);
                    mma16816(acc[i][2 * p + 1], af[i], bf[p & 1] + 2);
                }
                if (p < 2)
                    ldm_x4(bf[p & 1],
                           bbase + (uint32_t)((wn + (p + 2) * 16 + brow) * LDS_H + kc * 16 + bcol) * 2);
            }
            if (kc == 0) {
                if (kt + NST - 1 < nk) {
                    int s2 = (kt + NST - 1) % NST;
                    loadA(s2, (kt + NST - 1) * BK);
                    loadB(s2, (kt + NST - 1) * BK);
                }
                cpa_commit();
            }
        }
    }

    // epilogue (vectorized)
    __half* Ch = (__half*)Cv;
    float*  Cf = (float*)Cv;
    auto emit2 = [&](int r, long long c, float v0, float v1) {
        if (r < M) {
            if (EPI >= 1) {
                float2 b2 = *(const float2*)(bias + c);
                v0 += b2.x; v1 += b2.y;
            }
            if (EPI == 2) {
                v0 = 0.5f * v0 * (1.f + erff(v0 * 0.70710678118654752f));
                v1 = 0.5f * v1 * (1.f + erff(v1 * 0.70710678118654752f));
            }
            if (EPI >= 3) {
                float2 r2 = *(const float2*)(res + (long long)r * N + c);
                v0 += r2.x; v1 += r2.y;
                *(float2*)(Cf + (long long)r * N + c) = make_float2(v0, v1);
            } else {
                *(__half2*)(Ch + (long long)r * N + c) = __floats2half2_rn(v0, v1);
            }
        }
    };
    #pragma unroll
    for (int i = 0; i < 2; i++) {
        int r0 = m0 + wm + i * 16 + g;
        #pragma unroll
        for (int j = 0; j < 8; j++) {
            long long c0 = n0 + wn + j * 8 + 2 * tg;
            emit2(r0,     c0, acc[i][j][0], acc[i][j][1]);
            emit2(r0 + 8, c0, acc[i][j][2], acc[i][j][3]);
        }
    }

    // fused LN2: last CTA (of the 3 n-tiles) for this m-tile normalizes its rows
    if (EPI == 4) {
        __threadfence();
        __shared__ int s_last;
        if (tid == 0)
            s_last = (atomicAdd(&g_cnt[blockIdx.y], 1) == (int)gridDim.x - 1) ? 1 : 0;
        __syncthreads();
        if (s_last) {
            __threadfence();   // acquire: order peer-CTA x2 writes before our reads
            for (int rr = wid; rr < BM; rr += 16) {
                int row = m0 + rr;
                if (row < M)
                    ln_row(Cf + (long long)row * N, lnw, lnb,
                           hout + (long long)row * CD, lane);
            }
        }
    }
}

// =====================================================================
// flash attention: per (qtile, b*h). 256 threads, 8 warps x 16 q-rows.
// =====================================================================
constexpr int FP = 72;                    // padded halves per row
constexpr int FTILE = 128 * FP;           // halves per tile buffer
constexpr int FSMEM = 5 * FTILE * 2;      // Q + 2K + 2V = 92160 B
constexpr int NQT = (CS + 127) / 128;     // 5

__global__ void __launch_bounds__(256, 1) flash_k(
    const __half* __restrict__ qkv, __half* __restrict__ ctx)
{
    extern __shared__ __align__(16) __half fs[];
    uint32_t sbase = smem_u32(fs);

    int q0 = blockIdx.x * 128;
    int bh = blockIdx.y;
    int b = bh / CH, h = bh % CH;
    int tid = threadIdx.x, lane = tid & 31, wid = tid >> 5;
    int g = lane >> 2, tg = lane & 3;

    const __half* qbase = qkv + (long long)b * CS * (3 * CD) + h * CDH;

    uint32_t sQ = sbase;
    uint32_t sK[2] = { sbase + FTILE * 2u, sbase + FTILE * 4u };
    uint32_t sV[2] = { sbase + FTILE * 6u, sbase + FTILE * 8u };

    auto load_tile = [&](uint32_t dstb, const __half* src, int t0) {
        #pragma unroll
        for (int i = 0; i < 4; i++) {
            int v = tid + i * 256;
            int r = v >> 3, c8 = (v & 7) << 3;
            uint32_t dst = dstb + (uint32_t)(r * FP + c8) * 2;
            if (t0 + r < CS) cpa16s(dst, src + (long long)(t0 + r) * (3 * CD) + c8);
            else             sts_zero16(dst);
        }
    };

    load_tile(sQ, qbase, q0);
    load_tile(sK[0], qbase + CD, 0);
    load_tile(sV[0], qbase + 2 * CD, 0);
    cpa_commit();

    int arow = ((lane >> 3) & 1) * 8 + (lane & 7);
    int acol = (lane >> 4) * 8;
    int brow = ((lane >> 4) & 1) * 8 + (lane & 7);
    int bcol = ((lane >> 3) & 1) * 8;
    int trow = ((lane >> 3) & 1) * 8 + (lane & 7);
    int tcol = (lane >> 4) * 8;

    asm volatile("cp.async.wait_group 0;");
    __syncthreads();

    uint32_t af_q[4][4];
    {
        __half2 sc = __float2half2_rn(0.125f);
        #pragma unroll
        for (int ks = 0; ks < 4; ks++) {
            ldm_x4(af_q[ks], sQ + (uint32_t)((wid * 16 + arow) * FP + ks * 16 + acol) * 2);
            #pragma unroll
            for (int q = 0; q < 4; q++) {
                __half2 v = *(__half2*)&af_q[ks][q];
                v = __hmul2(v, sc);
                af_q[ks][q] = *(uint32_t*)&v;
            }
        }
    }

    float acc_o[8][4];
    #pragma unroll
    for (int j = 0; j < 8; j++)
        #pragma unroll
        for (int q = 0; q < 4; q++) acc_o[j][q] = 0.f;
    float m_lo = -1e30f, m_hi = -1e30f, l_lo = 0.f, l_hi = 0.f;

    for (int t = 0; t < NQT; t++) {
        int buf = t & 1;
        __syncthreads();
        if (t + 1 < NQT) {
            load_tile(sK[buf ^ 1], qbase + CD, (t + 1) * 128);
            load_tile(sV[buf ^ 1], qbase + 2 * CD, (t + 1) * 128);
            cpa_commit();
            asm volatile("cp.async.wait_group 1;");
        } else {
            asm volatile("cp.async.wait_group 0;");
        }
        __syncthreads();

        int valid = CS - t * 128;

        float s[16][4];
        #pragma unroll
        for (int j = 0; j < 16; j++)
            #pragma unroll
            for (int q = 0; q < 4; q++) s[j][q] = 0.f;
        #pragma unroll
        for (int ks = 0; ks < 4; ks++) {
            #pragma unroll
            for (int p = 0; p < 8; p++) {
                uint32_t bf[4];
                ldm_x4(bf, sK[buf] + (uint32_t)((p * 16 + brow) * FP + ks * 16 + bcol) * 2);
                mma16816(s[2 * p],     af_q[ks], bf);
                mma16816(s[2 * p + 1], af_q[ks], bf + 2);
            }
        }

        if (valid < 128) {
            #pragma unroll
            for (int j = 0; j < 16; j++) {
                int cc = j * 8 + 2 * tg;
                if (cc     >= valid) { s[j][0] = -1e30f; s[j][2] = -1e30f; }
                if (cc + 1 >= valid) { s[j][1] = -1e30f; s[j][3] = -1e30f; }
            }
        }

        float mx_lo = -1e30f, mx_hi = -1e30f;
        #pragma unroll
        for (int j = 0; j < 16; j++) {
            mx_lo = fmaxf(mx_lo, fmaxf(s[j][0], s[j][1]));
            mx_hi = fmaxf(mx_hi, fmaxf(s[j][2], s[j][3]));
        }
        mx_lo = fmaxf(mx_lo, __shfl_xor_sync(0xffffffffu, mx_lo, 1));
        mx_lo = fmaxf(mx_lo, __shfl_xor_sync(0xffffffffu, mx_lo, 2));
        mx_hi = fmaxf(mx_hi, __shfl_xor_sync(0xffffffffu, mx_hi, 1));
        mx_hi = fmaxf(mx_hi, __shfl_xor_sync(0xffffffffu, mx_hi, 2));

        float mn_lo = fmaxf(m_lo, mx_lo), mn_hi = fmaxf(m_hi, mx_hi);
        float corr_lo = __expf(m_lo - mn_lo), corr_hi = __expf(m_hi - mn_hi);
        m_lo = mn_lo; m_hi = mn_hi;

        float sum_lo = 0.f, sum_hi = 0.f;
        uint32_t pf[8][4];
        #pragma unroll
        for (int kt = 0; kt < 8; kt++) {
            float p00 = __expf(s[2 * kt][0] - mn_lo);
            float p01 = __expf(s[2 * kt][1] - mn_lo);
            float p02 = __expf(s[2 * kt][2] - mn_hi);
            float p03 = __expf(s[2 * kt][3] - mn_hi);
            float p10 = __expf(s[2 * kt + 1][0] - mn_lo);
            float p11 = __expf(s[2 * kt + 1][1] - mn_lo);
            float p12 = __expf(s[2 * kt + 1][2] - mn_hi);
            float p13 = __expf(s[2 * kt + 1][3] - mn_hi);
            sum_lo += p00 + p01 + p10 + p11;
            sum_hi += p02 + p03 + p12 + p13;
            __half2 h0 = __floats2half2_rn(p00, p01);
            __half2 h1 = __floats2half2_rn(p02, p03);
            __half2 h2 = __floats2half2_rn(p10, p11);
            __half2 h3 = __floats2half2_rn(p12, p13);
            pf[kt][0] = *(uint32_t*)&h0;
            pf[kt][1] = *(uint32_t*)&h1;
            pf[kt][2] = *(uint32_t*)&h2;
            pf[kt][3] = *(uint32_t*)&h3;
        }
        sum_lo += __shfl_xor_sync(0xffffffffu, sum_lo, 1);
        sum_lo += __shfl_xor_sync(0xffffffffu, sum_lo, 2);
        sum_hi += __shfl_xor_sync(0xffffffffu, sum_hi, 1);
        sum_hi += __shfl_xor_sync(0xffffffffu, sum_hi, 2);
        l_lo = l_lo * corr_lo + sum_lo;
        l_hi = l_hi * corr_hi + sum_hi;

        #pragma unroll
        for (int j = 0; j < 8; j++) {
            acc_o[j][0] *= corr_lo; acc_o[j][1] *= corr_lo;
            acc_o[j][2] *= corr_hi; acc_o[j][3] *= corr_hi;
        }

        #pragma unroll
        for (int kt = 0; kt < 8; kt++) {
            #pragma unroll
            for (int ep = 0; ep < 2; ep++) {
                uint32_t bf[4];
                ldm_x4_t(bf, sV[buf] + (uint32_t)((kt * 16 + trow) * FP + ep * 32 + tcol) * 2);
                mma16816(acc_o[4 * ep],     pf[kt], bf);
                mma16816(acc_o[4 * ep + 1], pf[kt], bf + 2);
            }
            #pragma unroll
            for (int ep = 0; ep < 2; ep++) {
                uint32_t bf[4];
                ldm_x4_t(bf, sV[buf] + (uint32_t)((kt * 16 + trow) * FP + ep * 32 + 16 + tcol) * 2);
                mma16816(acc_o[4 * ep + 2], pf[kt], bf);
                mma16816(acc_o[4 * ep + 3], pf[kt], bf + 2);
            }
        }
    }

    float il_lo = 1.f / l_lo, il_hi = 1.f / l_hi;
    int r_lo = q0 + wid * 16 + g;
    int r_hi = r_lo + 8;
    #pragma unroll
    for (int j = 0; j < 8; j++) {
        int cc = j * 8 + 2 * tg;
        if (r_lo < CS) {
            __half2 v = __floats2half2_rn(acc_o[j][0] * il_lo, acc_o[j][1] * il_lo);
            *(__half2*)(ctx + (long long)(b * CS + r_lo) * CD + h * CDH + cc) = v;
        }
        if (r_hi < CS) {
            __half2 v = __floats2half2_rn(acc_o[j][2] * il_hi, acc_o[j][3] * il_hi);
            *(__half2*)(ctx + (long long)(b * CS + r_hi) * CD + h * CDH + cc) = v;
        }
    }
}

// ---------------- launch ----------------
extern "C" void kernel_launch(void* const* d_in, const int* in_sizes, int n_in,
                              void* d_out, int out_size) {
    const float* x    = (const float*)d_in[0];
    const float* ln1w = (const float*)d_in[1];
    const float* ln1b = (const float*)d_in[2];
    const float* Wq   = (const float*)d_in[3];
    const float* bq   = (const float*)d_in[4];
    const float* Wk   = (const float*)d_in[5];
    const float* bk   = (const float*)d_in[6];
    const float* Wv   = (const float*)d_in[7];
    const float* bv   = (const float*)d_in[8];
    const float* Wo   = (const float*)d_in[9];
    const float* bo   = (const float*)d_in[10];
    const float* ln2w = (const float*)d_in[11];
    const float* ln2b = (const float*)d_in[12];
    const float* W1   = (const float*)d_in[13];
    const float* b1   = (const float*)d_in[14];
    const float* W2   = (const float*)d_in[15];
    const float* b2   = (const float*)d_in[16];
    float* out = (float*)d_out;

    __half *p_h, *p_qkv, *p_ctx, *p_ffn, *p_Wqkvt, *p_Wot, *p_W1t, *p_W2t;
    float *p_x2, *p_bqkv;
    cudaGetSymbolAddress((void**)&p_h,     g_h);
    cudaGetSymbolAddress((void**)&p_qkv,   g_qkv);
    cudaGetSymbolAddress((void**)&p_ctx,   g_ctx);
    cudaGetSymbolAddress((void**)&p_x2,    g_x2);
    cudaGetSymbolAddress((void**)&p_ffn,   g_ffn);
    cudaGetSymbolAddress((void**)&p_Wqkvt, g_Wqkvt);
    cudaGetSymbolAddress((void**)&p_bqkv,  g_bqkv);
    cudaGetSymbolAddress((void**)&p_Wot,   g_Wot);
    cudaGetSymbolAddress((void**)&p_W1t,   g_W1t);
    cudaGetSymbolAddress((void**)&p_W2t,   g_W2t);

    cudaFuncSetAttribute(hgemm2<1>, cudaFuncAttributeMaxDynamicSharedMemorySize, DSMEM);
    cudaFuncSetAttribute(hgemm2<2>, cudaFuncAttributeMaxDynamicSharedMemorySize, DSMEM);
    cudaFuncSetAttribute(hgemm2<4>, cudaFuncAttributeMaxDynamicSharedMemorySize, DSMEM);
    cudaFuncSetAttribute(hgemm2<3>, cudaFuncAttributeMaxDynamicSharedMemorySize, DSMEM);
    cudaFuncSetAttribute(flash_k,   cudaFuncAttributeMaxDynamicSharedMemorySize, FSMEM);

    // fused prep: weight transposes + bias pack + LN1 + counter reset
    prep_k<<<PREP_BLOCKS, 256>>>(Wq, Wk, Wv, bq, bk, bv, Wo, W1, W2, x, ln1w, ln1b);

    // QKV: [18464,768] x [2304,768]^T (+bias) -> fp16
    hgemm2<1><<<dim3(3 * CD / BN, MT), NTHR, DSMEM>>>(
        p_h, p_Wqkvt, p_qkv, p_bqkv, nullptr, MALL, 3 * CD, CD,
        nullptr, nullptr, nullptr);

    // fused attention -> ctx fp16
    flash_k<<<dim3(NQT, CB * CH), 256, FSMEM>>>(p_qkv, p_ctx);

    // x2 = ctx @ Wo + bo + x (fp32 out) + FUSED LN2 -> g_h
    hgemm2<4><<<dim3(CD / BN, MT), NTHR, DSMEM>>>(
        p_ctx, p_Wot, p_x2, bo, x, MALL, CD, CD,
        ln2w, ln2b, p_h);

    // ffn = GELU(h2 @ W1 + b1) -> fp16
    hgemm2<2><<<dim3(CFF / BN, MT), NTHR, DSMEM>>>(
        p_h, p_W1t, p_ffn, b1, nullptr, MALL, CFF, CD,
        nullptr, nullptr, nullptr);

    // out = ffn @ W2 + b2 + x2  (fp32 out)
    hgemm2<3><<<dim3(CD / BN, MT), NTHR, DSMEM>>>(
        p_ffn, p_W2t, out, b2, p_x2, MALL, CD, CFF,
        nullptr, nullptr, nullptr);
}

// round 17
// speedup vs baseline: 1.0265x; 1.0265x over previous
#include <cuda_runtime.h>
#include <cuda_fp16.h>
#include <cstdint>
#include <math.h>

#define DEVI __device__ __forceinline__

// ---------------- problem constants ----------------
constexpr int CB = 32, CS = 577, CD = 768, CH = 12, CDH = 64, CFF = 3072;
constexpr int MALL = CB * CS;            // 18464 rows
constexpr float LNEPS = 1e-5f;

// ---------------- device scratch (allocation-free) ----------------
__device__ __half g_h   [MALL * CD];              // LN out (GEMM A)
__device__ __half g_qkv [MALL * 3 * CD];          // q|k|v fp16, row ld = 2304
__device__ __half g_ctx [MALL * CD];              // attention ctx fp16
__device__ float  g_x2  [MALL * CD];              // x + attn_out (fp32 residual)
__device__ __half g_ffn [MALL * CFF];             // GELU out fp16
__device__ __half g_Wqkvt[3 * CD * CD];           // [2304][768] k-major
__device__ float  g_bqkv [3 * CD];
__device__ __half g_Wot  [CD * CD];               // [768][768] k-major
__device__ __half g_W1t  [CFF * CD];              // [3072][768]
__device__ __half g_W2t  [CD * CFF];              // [768][3072]

// ---------------- helpers ----------------
DEVI uint32_t smem_u32(const void* p) {
    uint32_t a;
    asm("{ .reg .u64 t; cvta.to.shared.u64 t, %1; cvt.u32.u64 %0, t; }" : "=r"(a) : "l"(p));
    return a;
}
DEVI void cpa16s(uint32_t dst, const void* g) {
    asm volatile("cp.async.cg.shared.global [%0], [%1], 16;" :: "r"(dst), "l"(g));
}
DEVI void cpa_commit() { asm volatile("cp.async.commit_group;"); }
DEVI void sts_zero16(uint32_t dst) {
    asm volatile("st.shared.v4.b32 [%0], {%1,%1,%1,%1};" :: "r"(dst), "r"(0));
}
DEVI void ldm_x4(uint32_t* r, uint32_t addr) {
    asm volatile("ldmatrix.sync.aligned.m8n8.x4.shared.b16 {%0,%1,%2,%3}, [%4];"
        : "=r"(r[0]), "=r"(r[1]), "=r"(r[2]), "=r"(r[3]) : "r"(addr));
}
DEVI void ldm_x4_t(uint32_t* r, uint32_t addr) {
    asm volatile("ldmatrix.sync.aligned.m8n8.x4.trans.shared.b16 {%0,%1,%2,%3}, [%4];"
        : "=r"(r[0]), "=r"(r[1]), "=r"(r[2]), "=r"(r[3]) : "r"(addr));
}
DEVI void mma16816(float* c, const uint32_t* a, const uint32_t* b) {
    asm volatile(
        "mma.sync.aligned.m16n8k16.row.col.f32.f16.f16.f32 "
        "{%0,%1,%2,%3},{%4,%5,%6,%7},{%8,%9},{%0,%1,%2,%3};"
        : "+f"(c[0]), "+f"(c[1]), "+f"(c[2]), "+f"(c[3])
        : "r"(a[0]), "r"(a[1]), "r"(a[2]), "r"(a[3]), "r"(b[0]), "r"(b[1]));
}

// ---------------- fused prep kernel: all weight transposes + bias + LN1 ----------------
constexpr int PREP_BLOCKS = 9223;

DEVI void tr32(const float* __restrict__ src, __half* __restrict__ dst,
               int R, int C, int xb, int yb, int tx, int ty, float* t) {
    int c0 = xb * 32, r0 = yb * 32;
    #pragma unroll
    for (int i = 0; i < 32; i += 8)
        t[(ty + i) * 33 + tx] = src[(long long)(r0 + ty + i) * C + c0 + tx];
    __syncthreads();
    #pragma unroll
    for (int i = 0; i < 32; i += 8)
        dst[(long long)(c0 + ty + i) * R + r0 + tx] = __float2half_rn(t[tx * 33 + ty + i]);
}

__global__ void __launch_bounds__(256) prep_k(
    const float* __restrict__ Wq, const float* __restrict__ Wk, const float* __restrict__ Wv,
    const float* __restrict__ bq, const float* __restrict__ bk, const float* __restrict__ bv,
    const float* __restrict__ Wo, const float* __restrict__ W1, const float* __restrict__ W2,
    const float* __restrict__ x, const float* __restrict__ ln1w, const float* __restrict__ ln1b)
{
    __shared__ float t[32 * 33];
    int bx = blockIdx.x;
    int tid = threadIdx.x, tx = tid & 31, ty = tid >> 5;

    if (bx < 1728) {
        int k0 = (bx % 24) * 32, n0 = (bx / 24) * 32;
        int which = n0 / CD;
        int c0 = n0 % CD, h = c0 >> 6, e0 = c0 & 63;
        const float* W = (which == 0) ? Wq : (which == 1) ? Wk : Wv;
        const float* base = W + (long long)h * CD * CDH;
        #pragma unroll
        for (int i = 0; i < 32; i += 8)
            t[(ty + i) * 33 + tx] = base[(long long)(k0 + ty + i) * CDH + e0 + tx];
        __syncthreads();
        #pragma unroll
        for (int i = 0; i < 32; i += 8)
            g_Wqkvt[(long long)(n0 + ty + i) * CD + k0 + tx] = __float2half_rn(t[tx * 33 + ty + i]);
    } else if (bx < 2304) {
        int idx = bx - 1728;
        tr32(Wo, g_Wot, CD, CD, idx % 24, idx / 24, tx, ty, t);
    } else if (bx < 4608) {
        int idx = bx - 2304;
        tr32(W1, g_W1t, CD, CFF, idx % 96, idx / 96, tx, ty, t);
    } else if (bx < 6912) {
        int idx = bx - 4608;
        tr32(W2, g_W2t, CFF, CD, idx % 24, idx / 24, tx, ty, t);
    } else if (bx < 6915) {
        int i = (bx - 6912) * 256 + tid;
        if (i < 3 * CD) {
            int w = i / CD, c = i % CD;
            g_bqkv[i] = ((w == 0) ? bq : (w == 1) ? bk : bv)[c];
        }
    } else {
        int row = (bx - 6915) * 8 + ty;
        if (row < MALL) {
            const float4* xr = (const float4*)(x + (long long)row * CD);
            float4 v[6];
            float s = 0.f;
            #pragma unroll
            for (int i = 0; i < 6; i++) {
                v[i] = xr[tx + 32 * i];
                s += (v[i].x + v[i].y) + (v[i].z + v[i].w);
            }
            #pragma unroll
            for (int o = 16; o > 0; o >>= 1) s += __shfl_xor_sync(0xffffffffu, s, o);
            float mu = s * (1.f / (float)CD);
            float q = 0.f;
            #pragma unroll
            for (int i = 0; i < 6; i++) {
                float dx = v[i].x - mu, dy = v[i].y - mu, dz = v[i].z - mu, dw = v[i].w - mu;
                q += dx * dx + dy * dy + dz * dz + dw * dw;
            }
            #pragma unroll
            for (int o = 16; o > 0; o >>= 1) q += __shfl_xor_sync(0xffffffffu, q, o);
            float rs = rsqrtf(q * (1.f / (float)CD) + LNEPS);
            __half* orow = g_h + (long long)row * CD;
            #pragma unroll
            for (int i = 0; i < 6; i++) {
                int c = (tx + 32 * i) * 4;
                float4 wv = *(const float4*)(ln1w + c);
                float4 bv = *(const float4*)(ln1b + c);
                *(__half2*)(orow + c) =
                    __floats2half2_rn((v[i].x - mu) * rs * wv.x + bv.x,
                                      (v[i].y - mu) * rs * wv.y + bv.y);
                *(__half2*)(orow + c + 2) =
                    __floats2half2_rn((v[i].z - mu) * rs * wv.z + bv.z,
                                      (v[i].w - mu) * rs * wv.w + bv.w);
            }
        }
    }
}

// ---------------- layer norm (standalone, for LN2) ----------------
__global__ void ln_k(const float* __restrict__ x, const float* __restrict__ w,
                     const float* __restrict__ b, __half* __restrict__ o) {
    int row = blockIdx.x * 8 + (threadIdx.x >> 5);
    int lane = threadIdx.x & 31;
    const float4* xr = (const float4*)(x + (long long)row * CD);
    float4 v[6];
    float s = 0.f;
    #pragma unroll
    for (int i = 0; i < 6; i++) {
        v[i] = xr[lane + 32 * i];
        s += (v[i].x + v[i].y) + (v[i].z + v[i].w);
    }
    #pragma unroll
    for (int t = 16; t > 0; t >>= 1) s += __shfl_xor_sync(0xffffffffu, s, t);
    float mu = s * (1.f / (float)CD);
    float q = 0.f;
    #pragma unroll
    for (int i = 0; i < 6; i++) {
        float dx = v[i].x - mu, dy = v[i].y - mu, dz = v[i].z - mu, dw = v[i].w - mu;
        q += dx * dx + dy * dy + dz * dz + dw * dw;
    }
    #pragma unroll
    for (int t = 16; t > 0; t >>= 1) q += __shfl_xor_sync(0xffffffffu, q, t);
    float rs = rsqrtf(q * (1.f / (float)CD) + LNEPS);
    __half* orow = o + (long long)row * CD;
    #pragma unroll
    for (int i = 0; i < 6; i++) {
        int c = (lane + 32 * i) * 4;
        float4 wv = *(const float4*)(w + c);
        float4 bv = *(const float4*)(b + c);
        *(__half2*)(orow + c) = __floats2half2_rn((v[i].x - mu) * rs * wv.x + bv.x,
                                                  (v[i].y - mu) * rs * wv.y + bv.y);
        *(__half2*)(orow + c + 2) = __floats2half2_rn((v[i].z - mu) * rs * wv.z + bv.z,
                                                      (v[i].w - mu) * rs * wv.w + bv.w);
    }
}

// =====================================================================
// big-tile fp16 GEMM: C[M,N] = A[M,K] * B[N,K]^T (+epilogue)
// 128x256x64, 16 warps x (32x64), rolling depth-2 B prefetch, 3-stage
// cp.async (166 KB smem; NST=4/221 KB kills the container — 3-for-3).
// Next-stage loads SPREAD across compute chunks: A after kc=0,
// B[0:2] after kc=1, B[2:4]+commit after kc=2.
// EPI: 1 = +bias, half out; 2 = +bias GELU, half out; 3 = +bias+res, float out
// =====================================================================
constexpr int BM = 128, BN = 256, BK = 64, NST = 3;
constexpr int NTHR = 512;
constexpr int LDS_H = BK + 8;              // 72 halves per row (144 B)
constexpr int ATILE = BM * LDS_H;
constexpr int BTILE = BN * LDS_H;
constexpr int STG_H = ATILE + BTILE;       // 27648 halves = 55296 B
constexpr int DSMEM = NST * STG_H * 2;     // 165888 B

template <int EPI>
__global__ void __launch_bounds__(NTHR, 1) hgemm2(
    const __half* __restrict__ A, const __half* __restrict__ B, void* __restrict__ Cv,
    const float* __restrict__ bias, const float* __restrict__ res,
    int M, int N, int K)
{
    extern __shared__ __align__(16) __half sh[];
    uint32_t sbase = smem_u32(sh);

    int m0 = blockIdx.y * BM;
    long long n0 = (long long)blockIdx.x * BN;
    int tid = threadIdx.x, lane = tid & 31, wid = tid >> 5;

    auto loadA = [&](int s, int k0) {
        uint32_t ab = sbase + (uint32_t)(s * STG_H) * 2;
        #pragma unroll
        for (int i = 0; i < 2; i++) {
            int v = tid + i * NTHR;
            int r = v >> 3, cq = (v & 7) << 3;
            uint32_t dst = ab + (uint32_t)(r * LDS_H + cq) * 2;
            int gm = m0 + r;
            if (gm < M) cpa16s(dst, A + (long long)gm * K + k0 + cq);
            else        sts_zero16(dst);
        }
    };
    // half = 0: B chunks 0,1 ; half = 1: B chunks 2,3
    auto loadBh = [&](int s, int k0, int half) {
        uint32_t bb = sbase + (uint32_t)(s * STG_H + ATILE) * 2;
        #pragma unroll
        for (int i = 0; i < 2; i++) {
            int v = tid + (half * 2 + i) * NTHR;
            int r = v >> 3, cq = (v & 7) << 3;
            uint32_t dst = bb + (uint32_t)(r * LDS_H + cq) * 2;
            cpa16s(dst, B + (n0 + r) * K + k0 + cq);
        }
    };

    int wm = (wid & 3) * 32;          // 0,32,64,96
    int wn = (wid >> 2) * 64;         // 0,64,128,192
    int g = lane >> 2, tg = lane & 3;

    int arow = ((lane >> 3) & 1) * 8 + (lane & 7);
    int acol = (lane >> 4) * 8;
    int brow = ((lane >> 4) & 1) * 8 + (lane & 7);
    int bcol = ((lane >> 3) & 1) * 8;

    float acc[2][8][4];
    #pragma unroll
    for (int i = 0; i < 2; i++)
        #pragma unroll
        for (int j = 0; j < 8; j++)
            #pragma unroll
            for (int q = 0; q < 4; q++) acc[i][j][q] = 0.f;

    int nk = K / BK;
    #pragma unroll
    for (int s = 0; s < NST - 1; s++) {
        loadA(s, s * BK);
        loadBh(s, s * BK, 0);
        loadBh(s, s * BK, 1);
        cpa_commit();
    }

    for (int kt = 0; kt < nk; kt++) {
        asm volatile("cp.async.wait_group %0;" :: "n"(NST - 2));
        __syncthreads();

        int st = kt % NST;
        uint32_t abase = sbase + (uint32_t)(st * STG_H) * 2;
        uint32_t bbase = sbase + (uint32_t)(st * STG_H + ATILE) * 2;

        bool pre = (kt + NST - 1 < nk);
        int s2 = (kt + NST - 1) % NST;
        int k2 = (kt + NST - 1) * BK;

        #pragma unroll
        for (int kc = 0; kc < 4; kc++) {
            uint32_t af[2][4];
            #pragma unroll
            for (int i = 0; i < 2; i++)
                ldm_x4(af[i], abase + (uint32_t)((wm + i * 16 + arow) * LDS_H + kc * 16 + acol) * 2);
            uint32_t bf[2][4];
            ldm_x4(bf[0], bbase + (uint32_t)((wn + 0 * 16 + brow) * LDS_H + kc * 16 + bcol) * 2);
            ldm_x4(bf[1], bbase + (uint32_t)((wn + 1 * 16 + brow) * LDS_H + kc * 16 + bcol) * 2);
            #pragma unroll
            for (int p = 0; p < 4; p++) {
                #pragma unroll
                for (int i = 0; i < 2; i++) {
                    mma16816(acc[i][2 * p],     af[i], bf[p & 1]);
                    mma16816(acc[i][2 * p + 1], af[i], bf[p & 1] + 2);
                }
                if (p < 2)
                    ldm_x4(bf[p & 1],
                           bbase + (uint32_t)((wn + (p + 2) * 16 + brow) * LDS_H + kc * 16 + bcol) * 2);
            }
            if (kc == 0 && pre) loadA(s2, k2);
            if (kc == 1 && pre) loadBh(s2, k2, 0);
            if (kc == 2) {
                if (pre) loadBh(s2, k2, 1);
                cpa_commit();
            }
        }
    }

    // epilogue (vectorized)
    __half* Ch = (__half*)Cv;
    float*  Cf = (float*)Cv;
    auto emit2 = [&](int r, long long c, float v0, float v1) {
        if (r < M) {
            if (EPI >= 1) {
                float2 b2 = *(const float2*)(bias + c);
                v0 += b2.x; v1 += b2.y;
            }
            if (EPI == 2) {
                v0 = 0.5f * v0 * (1.f + erff(v0 * 0.70710678118654752f));
                v1 = 0.5f * v1 * (1.f + erff(v1 * 0.70710678118654752f));
            }
            if (EPI == 3) {
                float2 r2 = *(const float2*)(res + (long long)r * N + c);
                v0 += r2.x; v1 += r2.y;
                *(float2*)(Cf + (long long)r * N + c) = make_float2(v0, v1);
            } else {
                *(__half2*)(Ch + (long long)r * N + c) = __floats2half2_rn(v0, v1);
            }
        }
    };
    #pragma unroll
    for (int i = 0; i < 2; i++) {
        int r0 = m0 + wm + i * 16 + g;
        #pragma unroll
        for (int j = 0; j < 8; j++) {
            long long c0 = n0 + wn + j * 8 + 2 * tg;
            emit2(r0,     c0, acc[i][j][0], acc[i][j][1]);
            emit2(r0 + 8, c0, acc[i][j][2], acc[i][j][3]);
        }
    }
}

// =====================================================================
// flash attention: per (qtile, b*h). 256 threads, 8 warps x 16 q-rows.
// =====================================================================
constexpr int FP = 72;                    // padded halves per row
constexpr int FTILE = 128 * FP;           // halves per tile buffer
constexpr int FSMEM = 5 * FTILE * 2;      // Q + 2K + 2V = 92160 B
constexpr int NQT = (CS + 127) / 128;     // 5

__global__ void __launch_bounds__(256, 1) flash_k(
    const __half* __restrict__ qkv, __half* __restrict__ ctx)
{
    extern __shared__ __align__(16) __half fs[];
    uint32_t sbase = smem_u32(fs);

    int q0 = blockIdx.x * 128;
    int bh = blockIdx.y;
    int b = bh / CH, h = bh % CH;
    int tid = threadIdx.x, lane = tid & 31, wid = tid >> 5;
    int g = lane >> 2, tg = lane & 3;

    const __half* qbase = qkv + (long long)b * CS * (3 * CD) + h * CDH;

    uint32_t sQ = sbase;
    uint32_t sK[2] = { sbase + FTILE * 2u, sbase + FTILE * 4u };
    uint32_t sV[2] = { sbase + FTILE * 6u, sbase + FTILE * 8u };

    auto load_tile = [&](uint32_t dstb, const __half* src, int t0) {
        #pragma unroll
        for (int i = 0; i < 4; i++) {
            int v = tid + i * 256;
            int r = v >> 3, c8 = (v & 7) << 3;
            uint32_t dst = dstb + (uint32_t)(r * FP + c8) * 2;
            if (t0 + r < CS) cpa16s(dst, src + (long long)(t0 + r) * (3 * CD) + c8);
            else             sts_zero16(dst);
        }
    };

    load_tile(sQ, qbase, q0);
    load_tile(sK[0], qbase + CD, 0);
    load_tile(sV[0], qbase + 2 * CD, 0);
    cpa_commit();

    int arow = ((lane >> 3) & 1) * 8 + (lane & 7);
    int acol = (lane >> 4) * 8;
    int brow = ((lane >> 4) & 1) * 8 + (lane & 7);
    int bcol = ((lane >> 3) & 1) * 8;
    int trow = ((lane >> 3) & 1) * 8 + (lane & 7);
    int tcol = (lane >> 4) * 8;

    asm volatile("cp.async.wait_group 0;");
    __syncthreads();

    uint32_t af_q[4][4];
    {
        __half2 sc = __float2half2_rn(0.125f);
        #pragma unroll
        for (int ks = 0; ks < 4; ks++) {
            ldm_x4(af_q[ks], sQ + (uint32_t)((wid * 16 + arow) * FP + ks * 16 + acol) * 2);
            #pragma unroll
            for (int q = 0; q < 4; q++) {
                __half2 v = *(__half2*)&af_q[ks][q];
                v = __hmul2(v, sc);
                af_q[ks][q] = *(uint32_t*)&v;
            }
        }
    }

    float acc_o[8][4];
    #pragma unroll
    for (int j = 0; j < 8; j++)
        #pragma unroll
        for (int q = 0; q < 4; q++) acc_o[j][q] = 0.f;
    float m_lo = -1e30f, m_hi = -1e30f, l_lo = 0.f, l_hi = 0.f;

    for (int t = 0; t < NQT; t++) {
        int buf = t & 1;
        __syncthreads();
        if (t + 1 < NQT) {
            load_tile(sK[buf ^ 1], qbase + CD, (t + 1) * 128);
            load_tile(sV[buf ^ 1], qbase + 2 * CD, (t + 1) * 128);
            cpa_commit();
            asm volatile("cp.async.wait_group 1;");
        } else {
            asm volatile("cp.async.wait_group 0;");
        }
        __syncthreads();

        int valid = CS - t * 128;

        float s[16][4];
        #pragma unroll
        for (int j = 0; j < 16; j++)
            #pragma unroll
            for (int q = 0; q < 4; q++) s[j][q] = 0.f;
        #pragma unroll
        for (int ks = 0; ks < 4; ks++) {
            #pragma unroll
            for (int p = 0; p < 8; p++) {
                uint32_t bf[4];
                ldm_x4(bf, sK[buf] + (uint32_t)((p * 16 + brow) * FP + ks * 16 + bcol) * 2);
                mma16816(s[2 * p],     af_q[ks], bf);
                mma16816(s[2 * p + 1], af_q[ks], bf + 2);
            }
        }

        if (valid < 128) {
            #pragma unroll
            for (int j = 0; j < 16; j++) {
                int cc = j * 8 + 2 * tg;
                if (cc     >= valid) { s[j][0] = -1e30f; s[j][2] = -1e30f; }
                if (cc + 1 >= valid) { s[j][1] = -1e30f; s[j][3] = -1e30f; }
            }
        }

        float mx_lo = -1e30f, mx_hi = -1e30f;
        #pragma unroll
        for (int j = 0; j < 16; j++) {
            mx_lo = fmaxf(mx_lo, fmaxf(s[j][0], s[j][1]));
            mx_hi = fmaxf(mx_hi, fmaxf(s[j][2], s[j][3]));
        }
        mx_lo = fmaxf(mx_lo, __shfl_xor_sync(0xffffffffu, mx_lo, 1));
        mx_lo = fmaxf(mx_lo, __shfl_xor_sync(0xffffffffu, mx_lo, 2));
        mx_hi = fmaxf(mx_hi, __shfl_xor_sync(0xffffffffu, mx_hi, 1));
        mx_hi = fmaxf(mx_hi, __shfl_xor_sync(0xffffffffu, mx_hi, 2));

        float mn_lo = fmaxf(m_lo, mx_lo), mn_hi = fmaxf(m_hi, mx_hi);
        float corr_lo = __expf(m_lo - mn_lo), corr_hi = __expf(m_hi - mn_hi);
        m_lo = mn_lo; m_hi = mn_hi;

        float sum_lo = 0.f, sum_hi = 0.f;
        uint32_t pf[8][4];
        #pragma unroll
        for (int kt = 0; kt < 8; kt++) {
            float p00 = __expf(s[2 * kt][0] - mn_lo);
            float p01 = __expf(s[2 * kt][1] - mn_lo);
            float p02 = __expf(s[2 * kt][2] - mn_hi);
            float p03 = __expf(s[2 * kt][3] - mn_hi);
            float p10 = __expf(s[2 * kt + 1][0] - mn_lo);
            float p11 = __expf(s[2 * kt + 1][1] - mn_lo);
            float p12 = __expf(s[2 * kt + 1][2] - mn_hi);
            float p13 = __expf(s[2 * kt + 1][3] - mn_hi);
            sum_lo += p00 + p01 + p10 + p11;
            sum_hi += p02 + p03 + p12 + p13;
            __half2 h0 = __floats2half2_rn(p00, p01);
            __half2 h1 = __floats2half2_rn(p02, p03);
            __half2 h2 = __floats2half2_rn(p10, p11);
            __half2 h3 = __floats2half2_rn(p12, p13);
            pf[kt][0] = *(uint32_t*)&h0;
            pf[kt][1] = *(uint32_t*)&h1;
            pf[kt][2] = *(uint32_t*)&h2;
            pf[kt][3] = *(uint32_t*)&h3;
        }
        sum_lo += __shfl_xor_sync(0xffffffffu, sum_lo, 1);
        sum_lo += __shfl_xor_sync(0xffffffffu, sum_lo, 2);
        sum_hi += __shfl_xor_sync(0xffffffffu, sum_hi, 1);
        sum_hi += __shfl_xor_sync(0xffffffffu, sum_hi, 2);
        l_lo = l_lo * corr_lo + sum_lo;
        l_hi = l_hi * corr_hi + sum_hi;

        #pragma unroll
        for (int j = 0; j < 8; j++) {
            acc_o[j][0] *= corr_lo; acc_o[j][1] *= corr_lo;
            acc_o[j][2] *= corr_hi; acc_o[j][3] *= corr_hi;
        }

        #pragma unroll
        for (int kt = 0; kt < 8; kt++) {
            #pragma unroll
            for (int ep = 0; ep < 2; ep++) {
                uint32_t bf[4];
                ldm_x4_t(bf, sV[buf] + (uint32_t)((kt * 16 + trow) * FP + ep * 32 + tcol) * 2);
                mma16816(acc_o[4 * ep],     pf[kt], bf);
                mma16816(acc_o[4 * ep + 1], pf[kt], bf + 2);
            }
            #pragma unroll
            for (int ep = 0; ep < 2; ep++) {
                uint32_t bf[4];
                ldm_x4_t(bf, sV[buf] + (uint32_t)((kt * 16 + trow) * FP + ep * 32 + 16 + tcol) * 2);
                mma16816(acc_o[4 * ep + 2], pf[kt], bf);
                mma16816(acc_o[4 * ep + 3], pf[kt], bf + 2);
            }
        }
    }

    float il_lo = 1.f / l_lo, il_hi = 1.f / l_hi;
    int r_lo = q0 + wid * 16 + g;
    int r_hi = r_lo + 8;
    #pragma unroll
    for (int j = 0; j < 8; j++) {
        int cc = j * 8 + 2 * tg;
        if (r_lo < CS) {
            __half2 v = __floats2half2_rn(acc_o[j][0] * il_lo, acc_o[j][1] * il_lo);
            *(__half2*)(ctx + (long long)(b * CS + r_lo) * CD + h * CDH + cc) = v;
        }
        if (r_hi < CS) {
            __half2 v = __floats2half2_rn(acc_o[j][2] * il_hi, acc_o[j][3] * il_hi);
            *(__half2*)(ctx + (long long)(b * CS + r_hi) * CD + h * CDH + cc) = v;
        }
    }
}

// ---------------- launch ----------------
extern "C" void kernel_launch(void* const* d_in, const int* in_sizes, int n_in,
                              void* d_out, int out_size) {
    const float* x    = (const float*)d_in[0];
    const float* ln1w = (const float*)d_in[1];
    const float* ln1b = (const float*)d_in[2];
    const float* Wq   = (const float*)d_in[3];
    const float* bq   = (const float*)d_in[4];
    const float* Wk   = (const float*)d_in[5];
    const float* bk   = (const float*)d_in[6];
    const float* Wv   = (const float*)d_in[7];
    const float* bv   = (const float*)d_in[8];
    const float* Wo   = (const float*)d_in[9];
    const float* bo   = (const float*)d_in[10];
    const float* ln2w = (const float*)d_in[11];
    const float* ln2b = (const float*)d_in[12];
    const float* W1   = (const float*)d_in[13];
    const float* b1   = (const float*)d_in[14];
    const float* W2   = (const float*)d_in[15];
    const float* b2   = (const float*)d_in[16];
    float* out = (float*)d_out;

    __half *p_h, *p_qkv, *p_ctx, *p_ffn, *p_Wqkvt, *p_Wot, *p_W1t, *p_W2t;
    float *p_x2, *p_bqkv;
    cudaGetSymbolAddress((void**)&p_h,     g_h);
    cudaGetSymbolAddress((void**)&p_qkv,   g_qkv);
    cudaGetSymbolAddress((void**)&p_ctx,   g_ctx);
    cudaGetSymbolAddress((void**)&p_x2,    g_x2);
    cudaGetSymbolAddress((void**)&p_ffn,   g_ffn);
    cudaGetSymbolAddress((void**)&p_Wqkvt, g_Wqkvt);
    cudaGetSymbolAddress((void**)&p_bqkv,  g_bqkv);
    cudaGetSymbolAddress((void**)&p_Wot,   g_Wot);
    cudaGetSymbolAddress((void**)&p_W1t,   g_W1t);
    cudaGetSymbolAddress((void**)&p_W2t,   g_W2t);

    cudaFuncSetAttribute(hgemm2<1>, cudaFuncAttributeMaxDynamicSharedMemorySize, DSMEM);
    cudaFuncSetAttribute(hgemm2<2>, cudaFuncAttributeMaxDynamicSharedMemorySize, DSMEM);
    cudaFuncSetAttribute(hgemm2<3>, cudaFuncAttributeMaxDynamicSharedMemorySize, DSMEM);
    cudaFuncSetAttribute(flash_k,   cudaFuncAttributeMaxDynamicSharedMemorySize, FSMEM);

    int mtiles = (MALL + BM - 1) / BM;   // 145

    // fused prep: all weight transposes + bias pack + LN1
    prep_k<<<PREP_BLOCKS, 256>>>(Wq, Wk, Wv, bq, bk, bv, Wo, W1, W2, x, ln1w, ln1b);

    // QKV: [18464,768] x [2304,768]^T (+bias) -> fp16
    hgemm2<1><<<dim3(3 * CD / BN, mtiles), NTHR, DSMEM>>>(
        p_h, p_Wqkvt, p_qkv, p_bqkv, nullptr, MALL, 3 * CD, CD);

    // fused attention -> ctx fp16
    flash_k<<<dim3(NQT, CB * CH), 256, FSMEM>>>(p_qkv, p_ctx);

    // x2 = ctx @ Wo + bo + x  (fp32 out)
    hgemm2<3><<<dim3(CD / BN, mtiles), NTHR, DSMEM>>>(
        p_ctx, p_Wot, p_x2, bo, x, MALL, CD, CD);

    // LN2 (warp-per-row)
    ln_k<<<MALL / 8, 256>>>(p_x2, ln2w, ln2b, p_h);

    // ffn = GELU(h2 @ W1 + b1) -> fp16
    hgemm2<2><<<dim3(CFF / BN, mtiles), NTHR, DSMEM>>>(
        p_h, p_W1t, p_ffn, b1, nullptr, MALL, CFF, CD);

    // out = ffn @ W2 + b2 + x2  (fp32 out)
    hgemm2<3><<<dim3(CD / BN, mtiles), NTHR, DSMEM>>>(
        p_ffn, p_W2t, out, b2, p_x2, MALL, CD, CFF);
}